// round 2
// baseline (speedup 1.0000x reference)
#include <cuda_runtime.h>
#include <math.h>

#define NA   512
#define OBSD 128
#define INP  656
#define HID  64
#define LAT  256
#define NH   64
#define LOG2PI 1.8378770664093453f
#define BNEPS 1e-5f

// ---------------- scratch (device globals; no allocation allowed) ----------------
__device__ float g_pre_e[NA*NH];
__device__ float g_pre_i[NA*NH];
__device__ float g_scale[2][NH], g_shift[2][NH];
__device__ float g_mu[NA*LAT], g_var[NA*LAT], g_logsig[NA*LAT];
__device__ float g_ni2v[NA*LAT], g_cc[NA*LAT], g_lat[NA*LAT];
__device__ float g_A[NA*NH], g_B[NA*NH];
__device__ float g_meanA[NH], g_meanB[NH], g_s2[NH];
__device__ float g_w1[NA*NH];
__device__ float g_mi[NA*NA], g_dis[NA*NA];
__device__ double g_ent, g_kl, g_sum_disn, g_sum_min;
__device__ float g_pmin[2][256], g_pmax[2][256];
__device__ float g_norm[4];   // mi_min, mi_inv, dis_min, dis_inv

// ---------------- init ----------------
__global__ void k_init() {
    g_ent = 0.0; g_kl = 0.0; g_sum_disn = 0.0; g_sum_min = 0.0;
}

// ---------------- encoder linear1: pre_e = obs[:, 528:656] @ eW1 + eb1 ----------------
__global__ void k_lin1_e(const float* __restrict__ obs,
                         const float* __restrict__ eW1,
                         const float* __restrict__ eb1) {
    int i = blockIdx.x, t = threadIdx.x;   // 128 threads
    __shared__ float s[OBSD];
    s[t] = obs[i*INP + (INP-OBSD) + t];
    __syncthreads();
    if (t < NH) {
        float acc = eb1[t];
        #pragma unroll 16
        for (int l = 0; l < OBSD; l++) acc = fmaf(s[l], eW1[l*NH + t], acc);
        g_pre_e[i*NH + t] = acc;
    }
}

// ---------------- inference linear1: pre_i = [hid, obs] @ iW1 + ib1 ----------------
__global__ void k_lin1_i(const float* __restrict__ obs,
                         const float* __restrict__ hid,
                         const float* __restrict__ iW1,
                         const float* __restrict__ ib1) {
    int i = blockIdx.x, t = threadIdx.x;   // 128 threads
    __shared__ float s[HID + INP];
    for (int l = t; l < HID; l += 128) s[l] = hid[i*HID + l];
    for (int l = t; l < INP; l += 128) s[HID + l] = obs[i*INP + l];
    __syncthreads();
    if (t < NH) {
        float acc = ib1[t];
        #pragma unroll 16
        for (int l = 0; l < HID + INP; l++) acc = fmaf(s[l], iW1[l*NH + t], acc);
        g_pre_i[i*NH + t] = acc;
    }
}

// ---------------- BN stats per column (axis=0 over 512 rows) ----------------
__global__ void k_bnstat(int which, const float* __restrict__ gamma,
                         const float* __restrict__ beta) {
    const float* pre = which ? g_pre_i : g_pre_e;
    int c = blockIdx.x, t = threadIdx.x;   // 256 threads
    __shared__ float red[256];
    float s = 0.f;
    for (int r = t; r < NA; r += 256) s += pre[r*NH + c];
    red[t] = s; __syncthreads();
    for (int o = 128; o; o >>= 1) { if (t < o) red[t] += red[t+o]; __syncthreads(); }
    float mean = red[0] * (1.f/NA);
    __syncthreads();
    float v = 0.f;
    for (int r = t; r < NA; r += 256) { float d = pre[r*NH + c] - mean; v += d*d; }
    red[t] = v; __syncthreads();
    for (int o = 128; o; o >>= 1) { if (t < o) red[t] += red[t+o]; __syncthreads(); }
    if (t == 0) {
        float var = red[0] * (1.f/NA);
        float sc = gamma[c] * rsqrtf(var + BNEPS);
        g_scale[which][c] = sc;
        g_shift[which][c] = beta[c] - mean*sc;
    }
}

// ---------------- encoder linear2 + latent head + entropy ----------------
__global__ void k_lat_e(const float* __restrict__ eW2,
                        const float* __restrict__ eb2,
                        const float* __restrict__ eps) {
    int i = blockIdx.x, t = threadIdx.x;   // 256 threads
    __shared__ float h[NH];
    __shared__ float red[256];
    if (t < NH) {
        float x = fmaf(g_pre_e[i*NH + t], g_scale[0][t], g_shift[0][t]);
        h[t] = (x > 0.f) ? x : 0.01f*x;
    }
    __syncthreads();
    float am = eb2[t], av = eb2[t + LAT];
    #pragma unroll
    for (int l = 0; l < NH; l++) {
        float hl = h[l];
        am = fmaf(hl, eW2[l*(2*LAT) + t], am);
        av = fmaf(hl, eW2[l*(2*LAT) + t + LAT], av);
    }
    float mu = am;
    float varv = fmaxf(expf(av), 0.002f);
    float logsig = 0.5f * logf(varv);
    int gi = i*LAT + t;
    g_mu[gi] = mu;
    g_var[gi] = varv;
    g_logsig[gi] = logsig;
    g_ni2v[gi] = -0.5f / varv;
    g_cc[gi] = 13.9f - logsig - 0.5f*LOG2PI;
    g_lat[gi] = fmaf(sqrtf(varv), eps[gi], mu);
    red[t] = 0.5f + 0.5f*LOG2PI + logsig;
    __syncthreads();
    for (int o = 128; o; o >>= 1) { if (t < o) red[t] += red[t+o]; __syncthreads(); }
    if (t == 0) atomicAdd(&g_ent, (double)red[0]);
}

// ---------------- inference linear2 + KL ----------------
__global__ void k_lat_i(const float* __restrict__ iW2,
                        const float* __restrict__ ib2) {
    int i = blockIdx.x, t = threadIdx.x;   // 256 threads
    __shared__ float h[NH];
    __shared__ float red[256];
    if (t < NH) {
        float x = fmaf(g_pre_i[i*NH + t], g_scale[1][t], g_shift[1][t]);
        h[t] = (x > 0.f) ? x : 0.01f*x;
    }
    __syncthreads();
    float am = ib2[t], av = ib2[t + LAT];
    #pragma unroll
    for (int l = 0; l < NH; l++) {
        float hl = h[l];
        am = fmaf(hl, iW2[l*(2*LAT) + t], am);
        av = fmaf(hl, iW2[l*(2*LAT) + t + LAT], av);
    }
    float mu_q = am;
    float var_q = fmaxf(expf(av), 0.002f);
    float lsq = 0.5f * logf(var_q);
    int gi = i*LAT + t;
    float dmu = g_mu[gi] - mu_q;
    float term = lsq - g_logsig[gi] + (g_var[gi] + dmu*dmu) / (2.f*var_q) - 0.5f;
    red[t] = term;
    __syncthreads();
    for (int o = 128; o; o >>= 1) { if (t < o) red[t] += red[t+o]; __syncthreads(); }
    if (t == 0) atomicAdd(&g_kl, (double)red[0]);
}

// ---------------- A = latent @ dW1[:256], B = latent @ dW1[256:] ----------------
__global__ void k_AB(const float* __restrict__ dW1) {
    int j = blockIdx.x, c = threadIdx.x;   // 64 threads
    __shared__ float L[LAT];
    for (int l = c; l < LAT; l += NH) L[l] = g_lat[j*LAT + l];
    __syncthreads();
    float a = 0.f, b = 0.f;
    #pragma unroll 8
    for (int l = 0; l < LAT; l++) {
        float lv = L[l];
        a = fmaf(lv, dW1[l*NH + c], a);
        b = fmaf(lv, dW1[(l + LAT)*NH + c], b);
    }
    g_A[j*NH + c] = a;
    g_B[j*NH + c] = b;
}

// ---------------- per-column means + sum of squared deviations ----------------
__global__ void k_ABstat() {
    int c = blockIdx.x, t = threadIdx.x;   // 256 threads
    __shared__ float rA[256], rB[256];
    float sA = 0.f, sB = 0.f;
    for (int r = t; r < NA; r += 256) { sA += g_A[r*NH + c]; sB += g_B[r*NH + c]; }
    rA[t] = sA; rB[t] = sB; __syncthreads();
    for (int o = 128; o; o >>= 1) { if (t < o) { rA[t] += rA[t+o]; rB[t] += rB[t+o]; } __syncthreads(); }
    float mA = rA[0] * (1.f/NA), mB = rB[0] * (1.f/NA);
    __syncthreads();
    float s2 = 0.f;
    for (int r = t; r < NA; r += 256) {
        float a = g_A[r*NH + c] - mA; float b = g_B[r*NH + c] - mB;
        s2 += a*a + b*b;
    }
    rA[t] = s2; __syncthreads();
    for (int o = 128; o; o >>= 1) { if (t < o) rA[t] += rA[t+o]; __syncthreads(); }
    if (t == 0) { g_meanA[c] = mA; g_meanB[c] = mB; g_s2[c] = rA[0] * (1.f/NA); }
}

// ---------------- center A,B in place ----------------
__global__ void k_center() {
    int idx = blockIdx.x*blockDim.x + threadIdx.x;   // 64*512 = 32768
    int c = idx & (NH-1);
    g_A[idx] -= g_meanA[c];
    g_B[idx] -= g_meanB[c];
}

// ---------------- circular correlation -> per-(s,c) BN scale ----------------
__global__ void k_cross(const float* __restrict__ dg) {
    int c = blockIdx.x, s = threadIdx.x;   // 512 threads
    __shared__ float a[NA], b[NA];
    a[s] = g_A[s*NH + c];
    b[s] = g_B[s*NH + c];
    __syncthreads();
    float cr = 0.f;
    #pragma unroll 8
    for (int j = 0; j < NA; j++) cr = fmaf(a[j], b[(j - s - 1) & (NA-1)], cr);
    float var = g_s2[c] + 2.f * cr * (1.f/NA);
    g_w1[s*NH + c] = dg[c] * rsqrtf(var + BNEPS);
}

// ---------------- MI: banded pairwise gaussian logp ----------------
__global__ void k_mi() {
    __shared__ float sMU[32][33], sNI[32][33], sCC[32][33];
    __shared__ float sL[64][33];
    int j0 = blockIdx.x * 32, s0 = blockIdx.y * 32;
    int tid = threadIdx.x;                 // 256
    int base = (j0 - s0 - 32) & (NA-1);
    int tx = tid & 15, ty = tid >> 4;
    int jj0 = 2*tx, ss0 = 2*ty;
    float acc00 = 0.f, acc01 = 0.f, acc10 = 0.f, acc11 = 0.f;
    for (int l0 = 0; l0 < LAT; l0 += 32) {
        #pragma unroll
        for (int i = 0; i < 4; i++) {
            int idx = tid + i*256;
            int r = idx >> 5, cc = idx & 31;
            int g = (j0 + r)*LAT + l0 + cc;
            sMU[r][cc] = g_mu[g]; sNI[r][cc] = g_ni2v[g]; sCC[r][cc] = g_cc[g];
        }
        #pragma unroll
        for (int i = 0; i < 8; i++) {
            int idx = tid + i*256;
            int r = idx >> 5, cc = idx & 31;
            sL[r][cc] = g_lat[((base + r) & (NA-1))*LAT + l0 + cc];
        }
        __syncthreads();
        #pragma unroll
        for (int l = 0; l < 32; l++) {
            float mu0 = sMU[jj0][l],   mu1 = sMU[jj0+1][l];
            float n0  = sNI[jj0][l],   n1  = sNI[jj0+1][l];
            float c0  = sCC[jj0][l],   c1  = sCC[jj0+1][l];
            // ss = ss0
            {
                float L0 = sL[jj0   - ss0 + 31][l];
                float L1 = sL[jj0+1 - ss0 + 31][l];
                float d0 = L0 - mu0; acc00 += fmaxf(fmaf(d0*d0, n0, c0), -13.9f);
                float d1 = L1 - mu1; acc01 += fmaxf(fmaf(d1*d1, n1, c1), -13.9f);
            }
            // ss = ss0+1
            {
                float L0 = sL[jj0   - ss0 + 30][l];
                float L1 = sL[jj0+1 - ss0 + 30][l];
                float d0 = L0 - mu0; acc10 += fmaxf(fmaf(d0*d0, n0, c0), -13.9f);
                float d1 = L1 - mu1; acc11 += fmaxf(fmaf(d1*d1, n1, c1), -13.9f);
            }
        }
        __syncthreads();
    }
    const float inv = 1.f / LAT;
    g_mi[(s0+ss0  )*NA + j0+jj0  ] = acc00 * inv;
    g_mi[(s0+ss0  )*NA + j0+jj0+1] = acc01 * inv;
    g_mi[(s0+ss0+1)*NA + j0+jj0  ] = acc10 * inv;
    g_mi[(s0+ss0+1)*NA + j0+jj0+1] = acc11 * inv;
}

// ---------------- DIS: discriminator with collapsed BN ----------------
__global__ void k_dis(const float* __restrict__ dbt,
                      const float* __restrict__ dW2,
                      const float* __restrict__ db2) {
    __shared__ float sa[32][65], sw[32][65], sb[64][65];
    __shared__ float sdbt[NH], sdw2[NH];
    int j0 = blockIdx.x * 32, s0 = blockIdx.y * 32;
    int tid = threadIdx.x;                 // 256
    int base = (j0 - s0 - 32) & (NA-1);
    if (tid < NH) { sdbt[tid] = dbt[tid]; sdw2[tid] = dW2[tid]; }
    #pragma unroll
    for (int i = 0; i < 8; i++) {
        int idx = tid + i*256;
        int r = idx >> 6, c = idx & 63;
        sa[r][c] = g_A[(j0 + r)*NH + c];
        sw[r][c] = g_w1[(s0 + r)*NH + c];
    }
    #pragma unroll
    for (int i = 0; i < 16; i++) {
        int idx = tid + i*256;
        int r = idx >> 6, c = idx & 63;
        sb[r][c] = g_B[((base + r) & (NA-1))*NH + c];
    }
    __syncthreads();
    int tx = tid & 15, ty = tid >> 4;
    int jj0 = 2*tx, ss0 = 2*ty;
    float acc00 = 0.f, acc01 = 0.f, acc10 = 0.f, acc11 = 0.f;
    #pragma unroll 8
    for (int c = 0; c < NH; c++) {
        float a0 = sa[jj0][c], a1 = sa[jj0+1][c];
        float w0 = sw[ss0][c], w1v = sw[ss0+1][c];
        float bt = sdbt[c], w2 = sdw2[c];
        {
            float b0 = sb[jj0   - ss0 + 31][c];
            float b1 = sb[jj0+1 - ss0 + 31][c];
            float v0 = fmaf(a0 + b0, w0, bt); v0 = (v0 > 0.f) ? v0 : 0.01f*v0;
            float v1 = fmaf(a1 + b1, w0, bt); v1 = (v1 > 0.f) ? v1 : 0.01f*v1;
            acc00 = fmaf(v0, w2, acc00);
            acc01 = fmaf(v1, w2, acc01);
        }
        {
            float b0 = sb[jj0   - ss0 + 30][c];
            float b1 = sb[jj0+1 - ss0 + 30][c];
            float v0 = fmaf(a0 + b0, w1v, bt); v0 = (v0 > 0.f) ? v0 : 0.01f*v0;
            float v1 = fmaf(a1 + b1, w1v, bt); v1 = (v1 > 0.f) ? v1 : 0.01f*v1;
            acc10 = fmaf(v0, w2, acc10);
            acc11 = fmaf(v1, w2, acc11);
        }
    }
    float b2 = db2[0];
    g_dis[(s0+ss0  )*NA + j0+jj0  ] = fabsf(acc00 + b2);
    g_dis[(s0+ss0  )*NA + j0+jj0+1] = fabsf(acc01 + b2);
    g_dis[(s0+ss0+1)*NA + j0+jj0  ] = fabsf(acc10 + b2);
    g_dis[(s0+ss0+1)*NA + j0+jj0+1] = fabsf(acc11 + b2);
}

// ---------------- min/max partials ----------------
__global__ void k_minmax() {
    int tid = threadIdx.x;
    int base = blockIdx.x * 1024;
    float mn0 = 1e30f, mx0 = -1e30f, mn1 = 1e30f, mx1 = -1e30f;
    #pragma unroll
    for (int i = 0; i < 4; i++) {
        int idx = base + tid + i*256;
        float a = g_mi[idx], d = g_dis[idx];
        mn0 = fminf(mn0, a); mx0 = fmaxf(mx0, a);
        mn1 = fminf(mn1, d); mx1 = fmaxf(mx1, d);
    }
    __shared__ float r0[256], r1[256], r2[256], r3[256];
    r0[tid] = mn0; r1[tid] = mx0; r2[tid] = mn1; r3[tid] = mx1;
    __syncthreads();
    for (int o = 128; o; o >>= 1) {
        if (tid < o) {
            r0[tid] = fminf(r0[tid], r0[tid+o]);
            r1[tid] = fmaxf(r1[tid], r1[tid+o]);
            r2[tid] = fminf(r2[tid], r2[tid+o]);
            r3[tid] = fmaxf(r3[tid], r3[tid+o]);
        }
        __syncthreads();
    }
    if (tid == 0) {
        g_pmin[0][blockIdx.x] = r0[0]; g_pmax[0][blockIdx.x] = r1[0];
        g_pmin[1][blockIdx.x] = r2[0]; g_pmax[1][blockIdx.x] = r3[0];
    }
}

__global__ void k_norm() {
    int tid = threadIdx.x;   // 256
    __shared__ float r0[256], r1[256], r2[256], r3[256];
    r0[tid] = g_pmin[0][tid]; r1[tid] = g_pmax[0][tid];
    r2[tid] = g_pmin[1][tid]; r3[tid] = g_pmax[1][tid];
    __syncthreads();
    for (int o = 128; o; o >>= 1) {
        if (tid < o) {
            r0[tid] = fminf(r0[tid], r0[tid+o]);
            r1[tid] = fmaxf(r1[tid], r1[tid+o]);
            r2[tid] = fminf(r2[tid], r2[tid+o]);
            r3[tid] = fmaxf(r3[tid], r3[tid+o]);
        }
        __syncthreads();
    }
    if (tid == 0) {
        g_norm[0] = r0[0];
        g_norm[1] = 1.f / (r1[0] - r0[0] + 1e-12f);
        g_norm[2] = r2[0];
        g_norm[3] = 1.f / (r3[0] - r2[0] + 1e-12f);
    }
}

// ---------------- normalized sums ----------------
__global__ void k_sums() {
    int tid = threadIdx.x;
    int base = blockIdx.x * 1024;
    float mi_min = g_norm[0], mi_inv = g_norm[1];
    float ds_min = g_norm[2], ds_inv = g_norm[3];
    double s1 = 0.0, s2 = 0.0;
    #pragma unroll
    for (int i = 0; i < 4; i++) {
        int idx = base + tid + i*256;
        float mi_n = (g_mi[idx] - mi_min) * mi_inv;
        float ds_n = (g_dis[idx] - ds_min) * ds_inv;
        s1 += (double)ds_n;
        s2 += (double)fminf(mi_n + ds_n, 1.0f);
    }
    __shared__ double d1[256], d2[256];
    d1[tid] = s1; d2[tid] = s2;
    __syncthreads();
    for (int o = 128; o; o >>= 1) {
        if (tid < o) { d1[tid] += d1[tid+o]; d2[tid] += d2[tid+o]; }
        __syncthreads();
    }
    if (tid == 0) {
        atomicAdd(&g_sum_disn, d1[0]);
        atomicAdd(&g_sum_min, d2[0]);
    }
}

// ---------------- final scalar assembly ----------------
__global__ void k_final(float* __restrict__ out) {
    double ent = g_ent / (double)NA;
    double kl  = g_kl  / (double)NA;
    double loss0 = fmin(ent*1e-4 + kl*1e-4, 2000.0);
    double ce = log1p(exp(loss0));
    double dis_norm = g_sum_disn / (double)NA;
    double dis_loss = -g_sum_min / (double)NA;
    double cdis = (dis_norm + dis_loss) / (double)NA;
    out[0] = (float)(ce + cdis);
    out[1] = (float)cdis;
    out[2] = (float)ce;
}

// ---------------- launcher ----------------
extern "C" void kernel_launch(void* const* d_in, const int* in_sizes, int n_in,
                              void* d_out, int out_size) {
    const float* obs  = (const float*)d_in[0];
    const float* hid  = (const float*)d_in[1];
    const float* eps  = (const float*)d_in[2];
    const float* eW1  = (const float*)d_in[3];
    const float* eb1  = (const float*)d_in[4];
    const float* eg   = (const float*)d_in[5];
    const float* ebt  = (const float*)d_in[6];
    const float* eW2  = (const float*)d_in[7];
    const float* eb2  = (const float*)d_in[8];
    const float* iW1  = (const float*)d_in[9];
    const float* ib1  = (const float*)d_in[10];
    const float* ig   = (const float*)d_in[11];
    const float* ibt  = (const float*)d_in[12];
    const float* iW2  = (const float*)d_in[13];
    const float* ib2  = (const float*)d_in[14];
    const float* dW1  = (const float*)d_in[15];
    const float* db1  = (const float*)d_in[16]; (void)db1; // cancels in BN
    const float* dg   = (const float*)d_in[17];
    const float* dbt  = (const float*)d_in[18];
    const float* dW2  = (const float*)d_in[19];
    const float* db2  = (const float*)d_in[20];
    float* out = (float*)d_out;

    k_init<<<1, 1>>>();
    k_lin1_e<<<NA, 128>>>(obs, eW1, eb1);
    k_lin1_i<<<NA, 128>>>(obs, hid, iW1, ib1);
    k_bnstat<<<NH, 256>>>(0, eg, ebt);
    k_bnstat<<<NH, 256>>>(1, ig, ibt);
    k_lat_e<<<NA, 256>>>(eW2, eb2, eps);
    k_lat_i<<<NA, 256>>>(iW2, ib2);
    k_AB<<<NA, NH>>>(dW1);
    k_ABstat<<<NH, 256>>>();
    k_center<<<64, 512>>>();
    k_cross<<<NH, NA>>>(dg);
    k_mi<<<dim3(16, 16), 256>>>();
    k_dis<<<dim3(16, 16), 256>>>(dbt, dW2, db2);
    k_minmax<<<256, 256>>>();
    k_norm<<<1, 256>>>();
    k_sums<<<256, 256>>>();
    k_final<<<1, 1>>>(out);
}

// round 3
// speedup vs baseline: 1.0028x; 1.0028x over previous
#include <cuda_runtime.h>
#include <math.h>

#define NA   512
#define OBSD 128
#define INP  656
#define HID  64
#define LAT  256
#define NH   64
#define LOG2PI 1.8378770664093453f
#define BNEPS 1e-5f

// ---------------- scratch (device globals; no allocation allowed) ----------------
__device__ float g_pre_e[NA*NH];
__device__ float g_pre_i[NA*NH];
__device__ float g_scale[2][NH], g_shift[2][NH];
__device__ float g_mu[NA*LAT], g_var[NA*LAT], g_logsig[NA*LAT];
__device__ float g_ni2v[NA*LAT], g_cc[NA*LAT], g_lat[NA*LAT];
__device__ float g_A[NA*NH], g_B[NA*NH];
__device__ float g_meanA[NH], g_meanB[NH], g_s2[NH];
__device__ float g_w1[NA*NH];
__device__ float g_mi[NA*NA], g_dis[NA*NA];
__device__ double g_ent, g_kl, g_sum_disn, g_sum_min;
__device__ float g_pmin[2][256], g_pmax[2][256];
__device__ float g_norm[4];   // mi_min, mi_inv, dis_min, dis_inv

// ---------------- init ----------------
__global__ void k_init() {
    g_ent = 0.0; g_kl = 0.0; g_sum_disn = 0.0; g_sum_min = 0.0;
}

// ---------------- encoder linear1: pre_e = obs[:, 528:656] @ eW1 + eb1 ----------------
__global__ void k_lin1_e(const float* __restrict__ obs,
                         const float* __restrict__ eW1,
                         const float* __restrict__ eb1) {
    int i = blockIdx.x, t = threadIdx.x;   // 128 threads
    __shared__ float s[OBSD];
    s[t] = obs[i*INP + (INP-OBSD) + t];
    __syncthreads();
    if (t < NH) {
        float acc = eb1[t];
        #pragma unroll 16
        for (int l = 0; l < OBSD; l++) acc = fmaf(s[l], eW1[l*NH + t], acc);
        g_pre_e[i*NH + t] = acc;
    }
}

// ---------------- inference linear1: pre_i = [hid, obs] @ iW1 + ib1 ----------------
__global__ void k_lin1_i(const float* __restrict__ obs,
                         const float* __restrict__ hid,
                         const float* __restrict__ iW1,
                         const float* __restrict__ ib1) {
    int i = blockIdx.x, t = threadIdx.x;   // 128 threads
    __shared__ float s[HID + INP];
    for (int l = t; l < HID; l += 128) s[l] = hid[i*HID + l];
    for (int l = t; l < INP; l += 128) s[HID + l] = obs[i*INP + l];
    __syncthreads();
    if (t < NH) {
        float acc = ib1[t];
        #pragma unroll 16
        for (int l = 0; l < HID + INP; l++) acc = fmaf(s[l], iW1[l*NH + t], acc);
        g_pre_i[i*NH + t] = acc;
    }
}

// ---------------- BN stats per column (axis=0 over 512 rows) ----------------
__global__ void k_bnstat(int which, const float* __restrict__ gamma,
                         const float* __restrict__ beta) {
    const float* pre = which ? g_pre_i : g_pre_e;
    int c = blockIdx.x, t = threadIdx.x;   // 256 threads
    __shared__ float red[256];
    float s = 0.f;
    for (int r = t; r < NA; r += 256) s += pre[r*NH + c];
    red[t] = s; __syncthreads();
    for (int o = 128; o; o >>= 1) { if (t < o) red[t] += red[t+o]; __syncthreads(); }
    float mean = red[0] * (1.f/NA);
    __syncthreads();
    float v = 0.f;
    for (int r = t; r < NA; r += 256) { float d = pre[r*NH + c] - mean; v += d*d; }
    red[t] = v; __syncthreads();
    for (int o = 128; o; o >>= 1) { if (t < o) red[t] += red[t+o]; __syncthreads(); }
    if (t == 0) {
        float var = red[0] * (1.f/NA);
        float sc = gamma[c] * rsqrtf(var + BNEPS);
        g_scale[which][c] = sc;
        g_shift[which][c] = beta[c] - mean*sc;
    }
}

// ---------------- encoder linear2 + latent head + entropy ----------------
__global__ void k_lat_e(const float* __restrict__ eW2,
                        const float* __restrict__ eb2,
                        const float* __restrict__ eps) {
    int i = blockIdx.x, t = threadIdx.x;   // 256 threads
    __shared__ float h[NH];
    __shared__ float red[256];
    if (t < NH) {
        float x = fmaf(g_pre_e[i*NH + t], g_scale[0][t], g_shift[0][t]);
        h[t] = (x > 0.f) ? x : 0.01f*x;
    }
    __syncthreads();
    float am = eb2[t], av = eb2[t + LAT];
    #pragma unroll
    for (int l = 0; l < NH; l++) {
        float hl = h[l];
        am = fmaf(hl, eW2[l*(2*LAT) + t], am);
        av = fmaf(hl, eW2[l*(2*LAT) + t + LAT], av);
    }
    float mu = am;
    float varv = fmaxf(expf(av), 0.002f);
    float logsig = 0.5f * logf(varv);
    int gi = i*LAT + t;
    g_mu[gi] = mu;
    g_var[gi] = varv;
    g_logsig[gi] = logsig;
    g_ni2v[gi] = -0.5f / varv;
    g_cc[gi] = 13.9f - logsig - 0.5f*LOG2PI;
    g_lat[gi] = fmaf(sqrtf(varv), eps[gi], mu);
    red[t] = 0.5f + 0.5f*LOG2PI + logsig;
    __syncthreads();
    for (int o = 128; o; o >>= 1) { if (t < o) red[t] += red[t+o]; __syncthreads(); }
    if (t == 0) atomicAdd(&g_ent, (double)red[0]);
}

// ---------------- inference linear2 + KL ----------------
__global__ void k_lat_i(const float* __restrict__ iW2,
                        const float* __restrict__ ib2) {
    int i = blockIdx.x, t = threadIdx.x;   // 256 threads
    __shared__ float h[NH];
    __shared__ float red[256];
    if (t < NH) {
        float x = fmaf(g_pre_i[i*NH + t], g_scale[1][t], g_shift[1][t]);
        h[t] = (x > 0.f) ? x : 0.01f*x;
    }
    __syncthreads();
    float am = ib2[t], av = ib2[t + LAT];
    #pragma unroll
    for (int l = 0; l < NH; l++) {
        float hl = h[l];
        am = fmaf(hl, iW2[l*(2*LAT) + t], am);
        av = fmaf(hl, iW2[l*(2*LAT) + t + LAT], av);
    }
    float mu_q = am;
    float var_q = fmaxf(expf(av), 0.002f);
    float lsq = 0.5f * logf(var_q);
    int gi = i*LAT + t;
    float dmu = g_mu[gi] - mu_q;
    float term = lsq - g_logsig[gi] + (g_var[gi] + dmu*dmu) / (2.f*var_q) - 0.5f;
    red[t] = term;
    __syncthreads();
    for (int o = 128; o; o >>= 1) { if (t < o) red[t] += red[t+o]; __syncthreads(); }
    if (t == 0) atomicAdd(&g_kl, (double)red[0]);
}

// ---------------- A = latent @ dW1[:256], B = latent @ dW1[256:] ----------------
__global__ void k_AB(const float* __restrict__ dW1) {
    int j = blockIdx.x, c = threadIdx.x;   // 64 threads
    __shared__ float L[LAT];
    for (int l = c; l < LAT; l += NH) L[l] = g_lat[j*LAT + l];
    __syncthreads();
    float a = 0.f, b = 0.f;
    #pragma unroll 8
    for (int l = 0; l < LAT; l++) {
        float lv = L[l];
        a = fmaf(lv, dW1[l*NH + c], a);
        b = fmaf(lv, dW1[(l + LAT)*NH + c], b);
    }
    g_A[j*NH + c] = a;
    g_B[j*NH + c] = b;
}

// ---------------- per-column means + sum of squared deviations ----------------
__global__ void k_ABstat() {
    int c = blockIdx.x, t = threadIdx.x;   // 256 threads
    __shared__ float rA[256], rB[256];
    float sA = 0.f, sB = 0.f;
    for (int r = t; r < NA; r += 256) { sA += g_A[r*NH + c]; sB += g_B[r*NH + c]; }
    rA[t] = sA; rB[t] = sB; __syncthreads();
    for (int o = 128; o; o >>= 1) { if (t < o) { rA[t] += rA[t+o]; rB[t] += rB[t+o]; } __syncthreads(); }
    float mA = rA[0] * (1.f/NA), mB = rB[0] * (1.f/NA);
    __syncthreads();
    float s2 = 0.f;
    for (int r = t; r < NA; r += 256) {
        float a = g_A[r*NH + c] - mA; float b = g_B[r*NH + c] - mB;
        s2 += a*a + b*b;
    }
    rA[t] = s2; __syncthreads();
    for (int o = 128; o; o >>= 1) { if (t < o) rA[t] += rA[t+o]; __syncthreads(); }
    if (t == 0) { g_meanA[c] = mA; g_meanB[c] = mB; g_s2[c] = rA[0] * (1.f/NA); }
}

// ---------------- center A,B in place ----------------
__global__ void k_center() {
    int idx = blockIdx.x*blockDim.x + threadIdx.x;   // 64*512 = 32768
    int c = idx & (NH-1);
    g_A[idx] -= g_meanA[c];
    g_B[idx] -= g_meanB[c];
}

// ---------------- circular correlation -> per-(s,c) BN scale ----------------
__global__ void k_cross(const float* __restrict__ dg) {
    int c = blockIdx.x, s = threadIdx.x;   // 512 threads
    __shared__ float a[NA], b[NA];
    a[s] = g_A[s*NH + c];
    b[s] = g_B[s*NH + c];
    __syncthreads();
    float cr = 0.f;
    #pragma unroll 8
    for (int j = 0; j < NA; j++) cr = fmaf(a[j], b[(j - s - 1) & (NA-1)], cr);
    float var = g_s2[c] + 2.f * cr * (1.f/NA);
    g_w1[s*NH + c] = dg[c] * rsqrtf(var + BNEPS);
}

// ---------------- MI: banded pairwise gaussian logp ----------------
__global__ void k_mi() {
    __shared__ float sMU[32][33], sNI[32][33], sCC[32][33];
    __shared__ float sL[64][33];
    int j0 = blockIdx.x * 32, s0 = blockIdx.y * 32;
    int tid = threadIdx.x;                 // 256
    int base = (j0 - s0 - 32) & (NA-1);
    int tx = tid & 15, ty = tid >> 4;
    int jj0 = 2*tx, ss0 = 2*ty;
    float acc00 = 0.f, acc01 = 0.f, acc10 = 0.f, acc11 = 0.f;
    for (int l0 = 0; l0 < LAT; l0 += 32) {
        #pragma unroll
        for (int i = 0; i < 4; i++) {
            int idx = tid + i*256;
            int r = idx >> 5, cc = idx & 31;
            int g = (j0 + r)*LAT + l0 + cc;
            sMU[r][cc] = g_mu[g]; sNI[r][cc] = g_ni2v[g]; sCC[r][cc] = g_cc[g];
        }
        #pragma unroll
        for (int i = 0; i < 8; i++) {
            int idx = tid + i*256;
            int r = idx >> 5, cc = idx & 31;
            sL[r][cc] = g_lat[((base + r) & (NA-1))*LAT + l0 + cc];
        }
        __syncthreads();
        #pragma unroll
        for (int l = 0; l < 32; l++) {
            float mu0 = sMU[jj0][l],   mu1 = sMU[jj0+1][l];
            float n0  = sNI[jj0][l],   n1  = sNI[jj0+1][l];
            float c0  = sCC[jj0][l],   c1  = sCC[jj0+1][l];
            // ss = ss0
            {
                float L0 = sL[jj0   - ss0 + 31][l];
                float L1 = sL[jj0+1 - ss0 + 31][l];
                float d0 = L0 - mu0; acc00 += fmaxf(fmaf(d0*d0, n0, c0), -13.9f);
                float d1 = L1 - mu1; acc01 += fmaxf(fmaf(d1*d1, n1, c1), -13.9f);
            }
            // ss = ss0+1
            {
                float L0 = sL[jj0   - ss0 + 30][l];
                float L1 = sL[jj0+1 - ss0 + 30][l];
                float d0 = L0 - mu0; acc10 += fmaxf(fmaf(d0*d0, n0, c0), -13.9f);
                float d1 = L1 - mu1; acc11 += fmaxf(fmaf(d1*d1, n1, c1), -13.9f);
            }
        }
        __syncthreads();
    }
    const float inv = 1.f / LAT;
    g_mi[(s0+ss0  )*NA + j0+jj0  ] = acc00 * inv;
    g_mi[(s0+ss0  )*NA + j0+jj0+1] = acc01 * inv;
    g_mi[(s0+ss0+1)*NA + j0+jj0  ] = acc10 * inv;
    g_mi[(s0+ss0+1)*NA + j0+jj0+1] = acc11 * inv;
}

// ---------------- DIS: discriminator with collapsed BN ----------------
__global__ void k_dis(const float* __restrict__ dbt,
                      const float* __restrict__ dW2,
                      const float* __restrict__ db2) {
    __shared__ float sa[32][65], sw[32][65], sb[64][65];
    __shared__ float sdbt[NH], sdw2[NH];
    int j0 = blockIdx.x * 32, s0 = blockIdx.y * 32;
    int tid = threadIdx.x;                 // 256
    int base = (j0 - s0 - 32) & (NA-1);
    if (tid < NH) { sdbt[tid] = dbt[tid]; sdw2[tid] = dW2[tid]; }
    #pragma unroll
    for (int i = 0; i < 8; i++) {
        int idx = tid + i*256;
        int r = idx >> 6, c = idx & 63;
        sa[r][c] = g_A[(j0 + r)*NH + c];
        sw[r][c] = g_w1[(s0 + r)*NH + c];
    }
    #pragma unroll
    for (int i = 0; i < 16; i++) {
        int idx = tid + i*256;
        int r = idx >> 6, c = idx & 63;
        sb[r][c] = g_B[((base + r) & (NA-1))*NH + c];
    }
    __syncthreads();
    int tx = tid & 15, ty = tid >> 4;
    int jj0 = 2*tx, ss0 = 2*ty;
    float acc00 = 0.f, acc01 = 0.f, acc10 = 0.f, acc11 = 0.f;
    #pragma unroll 8
    for (int c = 0; c < NH; c++) {
        float a0 = sa[jj0][c], a1 = sa[jj0+1][c];
        float w0 = sw[ss0][c], w1v = sw[ss0+1][c];
        float bt = sdbt[c], w2 = sdw2[c];
        {
            float b0 = sb[jj0   - ss0 + 31][c];
            float b1 = sb[jj0+1 - ss0 + 31][c];
            float v0 = fmaf(a0 + b0, w0, bt); v0 = (v0 > 0.f) ? v0 : 0.01f*v0;
            float v1 = fmaf(a1 + b1, w0, bt); v1 = (v1 > 0.f) ? v1 : 0.01f*v1;
            acc00 = fmaf(v0, w2, acc00);
            acc01 = fmaf(v1, w2, acc01);
        }
        {
            float b0 = sb[jj0   - ss0 + 30][c];
            float b1 = sb[jj0+1 - ss0 + 30][c];
            float v0 = fmaf(a0 + b0, w1v, bt); v0 = (v0 > 0.f) ? v0 : 0.01f*v0;
            float v1 = fmaf(a1 + b1, w1v, bt); v1 = (v1 > 0.f) ? v1 : 0.01f*v1;
            acc10 = fmaf(v0, w2, acc10);
            acc11 = fmaf(v1, w2, acc11);
        }
    }
    float b2 = db2[0];
    g_dis[(s0+ss0  )*NA + j0+jj0  ] = fabsf(acc00 + b2);
    g_dis[(s0+ss0  )*NA + j0+jj0+1] = fabsf(acc01 + b2);
    g_dis[(s0+ss0+1)*NA + j0+jj0  ] = fabsf(acc10 + b2);
    g_dis[(s0+ss0+1)*NA + j0+jj0+1] = fabsf(acc11 + b2);
}

// ---------------- min/max partials ----------------
__global__ void k_minmax() {
    int tid = threadIdx.x;
    int base = blockIdx.x * 1024;
    float mn0 = 1e30f, mx0 = -1e30f, mn1 = 1e30f, mx1 = -1e30f;
    #pragma unroll
    for (int i = 0; i < 4; i++) {
        int idx = base + tid + i*256;
        float a = g_mi[idx], d = g_dis[idx];
        mn0 = fminf(mn0, a); mx0 = fmaxf(mx0, a);
        mn1 = fminf(mn1, d); mx1 = fmaxf(mx1, d);
    }
    __shared__ float r0[256], r1[256], r2[256], r3[256];
    r0[tid] = mn0; r1[tid] = mx0; r2[tid] = mn1; r3[tid] = mx1;
    __syncthreads();
    for (int o = 128; o; o >>= 1) {
        if (tid < o) {
            r0[tid] = fminf(r0[tid], r0[tid+o]);
            r1[tid] = fmaxf(r1[tid], r1[tid+o]);
            r2[tid] = fminf(r2[tid], r2[tid+o]);
            r3[tid] = fmaxf(r3[tid], r3[tid+o]);
        }
        __syncthreads();
    }
    if (tid == 0) {
        g_pmin[0][blockIdx.x] = r0[0]; g_pmax[0][blockIdx.x] = r1[0];
        g_pmin[1][blockIdx.x] = r2[0]; g_pmax[1][blockIdx.x] = r3[0];
    }
}

__global__ void k_norm() {
    int tid = threadIdx.x;   // 256
    __shared__ float r0[256], r1[256], r2[256], r3[256];
    r0[tid] = g_pmin[0][tid]; r1[tid] = g_pmax[0][tid];
    r2[tid] = g_pmin[1][tid]; r3[tid] = g_pmax[1][tid];
    __syncthreads();
    for (int o = 128; o; o >>= 1) {
        if (tid < o) {
            r0[tid] = fminf(r0[tid], r0[tid+o]);
            r1[tid] = fmaxf(r1[tid], r1[tid+o]);
            r2[tid] = fminf(r2[tid], r2[tid+o]);
            r3[tid] = fmaxf(r3[tid], r3[tid+o]);
        }
        __syncthreads();
    }
    if (tid == 0) {
        g_norm[0] = r0[0];
        g_norm[1] = 1.f / (r1[0] - r0[0] + 1e-12f);
        g_norm[2] = r2[0];
        g_norm[3] = 1.f / (r3[0] - r2[0] + 1e-12f);
    }
}

// ---------------- normalized sums ----------------
__global__ void k_sums() {
    int tid = threadIdx.x;
    int base = blockIdx.x * 1024;
    float mi_min = g_norm[0], mi_inv = g_norm[1];
    float ds_min = g_norm[2], ds_inv = g_norm[3];
    double s1 = 0.0, s2 = 0.0;
    #pragma unroll
    for (int i = 0; i < 4; i++) {
        int idx = base + tid + i*256;
        float mi_n = (g_mi[idx] - mi_min) * mi_inv;
        float ds_n = (g_dis[idx] - ds_min) * ds_inv;
        s1 += (double)ds_n;
        s2 += (double)fminf(mi_n + ds_n, 1.0f);
    }
    __shared__ double d1[256], d2[256];
    d1[tid] = s1; d2[tid] = s2;
    __syncthreads();
    for (int o = 128; o; o >>= 1) {
        if (tid < o) { d1[tid] += d1[tid+o]; d2[tid] += d2[tid+o]; }
        __syncthreads();
    }
    if (tid == 0) {
        atomicAdd(&g_sum_disn, d1[0]);
        atomicAdd(&g_sum_min, d2[0]);
    }
}

// ---------------- final scalar assembly ----------------
__global__ void k_final(float* __restrict__ out) {
    double ent = g_ent / (double)NA;
    double kl  = g_kl  / (double)NA;
    double loss0 = fmin(ent*1e-4 + kl*1e-4, 2000.0);
    double ce = log1p(exp(loss0));
    double dis_norm = g_sum_disn / (double)NA;
    double dis_loss = -g_sum_min / (double)NA;
    double cdis = (dis_norm + dis_loss) / (double)NA;
    out[0] = (float)(ce + cdis);
    out[1] = (float)cdis;
    out[2] = (float)ce;
}

// ---------------- launcher ----------------
extern "C" void kernel_launch(void* const* d_in, const int* in_sizes, int n_in,
                              void* d_out, int out_size) {
    const float* obs  = (const float*)d_in[0];
    const float* hid  = (const float*)d_in[1];
    const float* eps  = (const float*)d_in[2];
    const float* eW1  = (const float*)d_in[3];
    const float* eb1  = (const float*)d_in[4];
    const float* eg   = (const float*)d_in[5];
    const float* ebt  = (const float*)d_in[6];
    const float* eW2  = (const float*)d_in[7];
    const float* eb2  = (const float*)d_in[8];
    const float* iW1  = (const float*)d_in[9];
    const float* ib1  = (const float*)d_in[10];
    const float* ig   = (const float*)d_in[11];
    const float* ibt  = (const float*)d_in[12];
    const float* iW2  = (const float*)d_in[13];
    const float* ib2  = (const float*)d_in[14];
    const float* dW1  = (const float*)d_in[15];
    const float* db1  = (const float*)d_in[16]; (void)db1; // cancels in BN
    const float* dg   = (const float*)d_in[17];
    const float* dbt  = (const float*)d_in[18];
    const float* dW2  = (const float*)d_in[19];
    const float* db2  = (const float*)d_in[20];
    float* out = (float*)d_out;

    k_init<<<1, 1>>>();
    k_lin1_e<<<NA, 128>>>(obs, eW1, eb1);
    k_lin1_i<<<NA, 128>>>(obs, hid, iW1, ib1);
    k_bnstat<<<NH, 256>>>(0, eg, ebt);
    k_bnstat<<<NH, 256>>>(1, ig, ibt);
    k_lat_e<<<NA, 256>>>(eW2, eb2, eps);
    k_lat_i<<<NA, 256>>>(iW2, ib2);
    k_AB<<<NA, NH>>>(dW1);
    k_ABstat<<<NH, 256>>>();
    k_center<<<64, 512>>>();
    k_cross<<<NH, NA>>>(dg);
    k_mi<<<dim3(16, 16), 256>>>();
    k_dis<<<dim3(16, 16), 256>>>(dbt, dW2, db2);
    k_minmax<<<256, 256>>>();
    k_norm<<<1, 256>>>();
    k_sums<<<256, 256>>>();
    k_final<<<1, 1>>>(out);
}